// round 1
// baseline (speedup 1.0000x reference)
#include <cuda_runtime.h>
#include <cuda_bf16.h>

#define N_NODES 50000
#define E_EDGES 400000
#define E_TOT   450000   // edges + self loops
#define G_GRAPHS 256
#define HC 200           // H*C
#define C_CH 100
#define F_IN 336
#define SLOPE 0.2f

// ---------------- scratch (device globals: no allocation allowed) -------------
__device__ float g_x[N_NODES * HC];       // layer output (post-relu)
__device__ float g_h[N_NODES * HC];       // per-layer linear output
__device__ float g_es[N_NODES * 2];
__device__ float g_ed[N_NODES * 2];
__device__ float g_alpha[E_TOT * 2];
__device__ int   g_cnt[N_NODES];
__device__ int   g_rowptr[N_NODES + 1];
__device__ int   g_wr[N_NODES];
__device__ int   g_srcidx[E_TOT];
__device__ float g_pool[G_GRAPHS * HC];
__device__ int   g_pcnt[G_GRAPHS];
__device__ float g_t1[G_GRAPHS * 100];
__device__ float g_t2[G_GRAPHS * 100];

// ---------------- CSR build ---------------------------------------------------
__global__ void k_init_cnt() {
    int i = blockIdx.x * blockDim.x + threadIdx.x;
    if (i < N_NODES) g_cnt[i] = 1;   // self-loop
}

__global__ void k_count(const int* __restrict__ ei) {
    int e = blockIdx.x * blockDim.x + threadIdx.x;
    if (e < E_EDGES) atomicAdd(&g_cnt[ei[E_EDGES + e]], 1);
}

__global__ void k_scan() {   // single block, 1024 threads
    const int n = N_NODES;
    int t = threadIdx.x;
    const int CHUNK = (n + 1023) / 1024;
    int start = t * CHUNK;
    int end = min(start + CHUNK, n);
    int sum = 0;
    for (int i = start; i < end; i++) sum += g_cnt[i];
    __shared__ int sh[1024];
    sh[t] = sum;
    __syncthreads();
    for (int off = 1; off < 1024; off <<= 1) {
        int v = (t >= off) ? sh[t - off] : 0;
        __syncthreads();
        sh[t] += v;
        __syncthreads();
    }
    int run = sh[t] - sum;   // exclusive
    for (int i = start; i < end; i++) {
        g_rowptr[i] = run;
        g_wr[i] = run;
        run += g_cnt[i];
    }
    if (t == 1023) g_rowptr[n] = sh[1023];
}

__global__ void k_scatter(const int* __restrict__ ei) {
    int e = blockIdx.x * blockDim.x + threadIdx.x;
    if (e >= E_TOT) return;
    int s, d;
    if (e < E_EDGES) { s = ei[e]; d = ei[E_EDGES + e]; }
    else             { s = d = e - E_EDGES; }
    int pos = atomicAdd(&g_wr[d], 1);
    g_srcidx[pos] = s;
}

// ---------------- SGEMM: C[M,Nn] = A[M,K] @ B[K,Nn] ---------------------------
__global__ void k_sgemm(const float* __restrict__ A, const float* __restrict__ B,
                        float* __restrict__ C, int M, int K, int Nn)
{
    const int BM = 64, BN = 64, BK = 16;
    __shared__ float As[BK][BM + 1];
    __shared__ float Bs[BK][BN + 1];
    int tid  = threadIdx.x;            // 256
    int trow = tid / 16;               // 0..15
    int tcol = tid % 16;               // 0..15
    int rowBase = blockIdx.y * BM;
    int colBase = blockIdx.x * BN;
    float acc[4][4] = {};

    for (int k0 = 0; k0 < K; k0 += BK) {
        for (int i = tid; i < BM * BK; i += 256) {
            int m = i >> 4, k = i & 15;
            int gm = rowBase + m, gk = k0 + k;
            As[k][m] = (gm < M && gk < K) ? A[gm * K + gk] : 0.f;
        }
        for (int i = tid; i < BK * BN; i += 256) {
            int k = i >> 6, nn = i & 63;
            int gk = k0 + k, gn = colBase + nn;
            Bs[k][nn] = (gk < K && gn < Nn) ? B[gk * Nn + gn] : 0.f;
        }
        __syncthreads();
#pragma unroll
        for (int k = 0; k < BK; k++) {
            float ar[4], br[4];
#pragma unroll
            for (int i = 0; i < 4; i++) ar[i] = As[k][trow * 4 + i];
#pragma unroll
            for (int j = 0; j < 4; j++) br[j] = Bs[k][tcol * 4 + j];
#pragma unroll
            for (int i = 0; i < 4; i++)
#pragma unroll
                for (int j = 0; j < 4; j++)
                    acc[i][j] += ar[i] * br[j];
        }
        __syncthreads();
    }
#pragma unroll
    for (int i = 0; i < 4; i++) {
        int gm = rowBase + trow * 4 + i;
        if (gm >= M) continue;
#pragma unroll
        for (int j = 0; j < 4; j++) {
            int gn = colBase + tcol * 4 + j;
            if (gn < Nn) C[gm * Nn + gn] = acc[i][j];
        }
    }
}

// ---------------- attention source/dest scores (warp per node) ----------------
__global__ void k_scores(const float* __restrict__ asrc, const float* __restrict__ adst) {
    int gwarp = (blockIdx.x * blockDim.x + threadIdx.x) >> 5;
    int lane  = threadIdx.x & 31;
    if (gwarp >= N_NODES) return;
    const float* hr = g_h + (long)gwarp * HC;
    float es0 = 0.f, es1 = 0.f, ed0 = 0.f, ed1 = 0.f;
    for (int c = lane; c < HC; c += 32) {
        float v = hr[c], a = asrc[c], d = adst[c];
        if (c < C_CH) { es0 += v * a; ed0 += v * d; }
        else          { es1 += v * a; ed1 += v * d; }
    }
#pragma unroll
    for (int o = 16; o; o >>= 1) {
        es0 += __shfl_xor_sync(0xffffffffu, es0, o);
        es1 += __shfl_xor_sync(0xffffffffu, es1, o);
        ed0 += __shfl_xor_sync(0xffffffffu, ed0, o);
        ed1 += __shfl_xor_sync(0xffffffffu, ed1, o);
    }
    if (lane == 0) {
        g_es[gwarp * 2]     = es0;
        g_es[gwarp * 2 + 1] = es1;
        g_ed[gwarp * 2]     = ed0;
        g_ed[gwarp * 2 + 1] = ed1;
    }
}

// ---------------- softmax + aggregate + bias + relu (warp per dst) ------------
__device__ __forceinline__ float lrelu(float e) { return e > 0.f ? e : SLOPE * e; }

__global__ void k_aggregate(const float* __restrict__ bc) {
    int gwarp = (blockIdx.x * blockDim.x + threadIdx.x) >> 5;
    int lane  = threadIdx.x & 31;
    if (gwarp >= N_NODES) return;
    int dst = gwarp;
    int beg = g_rowptr[dst], end = g_rowptr[dst + 1];
    float ed0 = g_ed[dst * 2], ed1 = g_ed[dst * 2 + 1];

    float m0 = -1e30f, m1 = -1e30f;
    for (int i = beg + lane; i < end; i += 32) {
        int s = g_srcidx[i];
        m0 = fmaxf(m0, lrelu(g_es[s * 2]     + ed0));
        m1 = fmaxf(m1, lrelu(g_es[s * 2 + 1] + ed1));
    }
#pragma unroll
    for (int o = 16; o; o >>= 1) {
        m0 = fmaxf(m0, __shfl_xor_sync(0xffffffffu, m0, o));
        m1 = fmaxf(m1, __shfl_xor_sync(0xffffffffu, m1, o));
    }

    float s0 = 0.f, s1 = 0.f;
    for (int i = beg + lane; i < end; i += 32) {
        int s = g_srcidx[i];
        float p0 = __expf(lrelu(g_es[s * 2]     + ed0) - m0);
        float p1 = __expf(lrelu(g_es[s * 2 + 1] + ed1) - m1);
        g_alpha[i * 2]     = p0;
        g_alpha[i * 2 + 1] = p1;
        s0 += p0; s1 += p1;
    }
#pragma unroll
    for (int o = 16; o; o >>= 1) {
        s0 += __shfl_xor_sync(0xffffffffu, s0, o);
        s1 += __shfl_xor_sync(0xffffffffu, s1, o);
    }
    float inv0 = 1.f / (s0 + 1e-16f);
    float inv1 = 1.f / (s1 + 1e-16f);

    float acc[7] = {0.f, 0.f, 0.f, 0.f, 0.f, 0.f, 0.f};
    for (int i = beg; i < end; i++) {
        int s = g_srcidx[i];
        float a0 = g_alpha[i * 2]     * inv0;
        float a1 = g_alpha[i * 2 + 1] * inv1;
        const float* hr = g_h + (long)s * HC;
#pragma unroll
        for (int k = 0; k < 7; k++) {
            int c = lane + k * 32;
            if (c < HC) acc[k] += (c < C_CH ? a0 : a1) * hr[c];
        }
    }
#pragma unroll
    for (int k = 0; k < 7; k++) {
        int c = lane + k * 32;
        if (c < HC) g_x[(long)dst * HC + c] = fmaxf(acc[k] + bc[c], 0.f);
    }
}

// ---------------- mean pool ---------------------------------------------------
__global__ void k_pool_zero() {
    int i = blockIdx.x * blockDim.x + threadIdx.x;
    if (i < G_GRAPHS * HC) g_pool[i] = 0.f;
    if (i < G_GRAPHS) g_pcnt[i] = 0;
}

__global__ void k_pool(const int* __restrict__ batch) {
    int i = blockIdx.x * blockDim.x + threadIdx.x;
    if (i >= N_NODES * HC) return;
    int n = i / HC, c = i - n * HC;
    int b = batch[n];
    atomicAdd(&g_pool[b * HC + c], g_x[i]);
    if (c == 0) atomicAdd(&g_pcnt[b], 1);
}

// ---------------- tiny MLP layer (one block per graph) ------------------------
__global__ void k_mlp(const float* __restrict__ A, const float* __restrict__ Wm,
                      const float* __restrict__ bm, float* __restrict__ out,
                      int K, int Nn, int do_relu, int do_div) {
    int g = blockIdx.x;
    __shared__ float arow[HC];
    float inv = 1.f;
    if (do_div) inv = 1.f / fmaxf((float)g_pcnt[g], 1.f);
    for (int i = threadIdx.x; i < K; i += blockDim.x) arow[i] = A[g * K + i] * inv;
    __syncthreads();
    for (int j = threadIdx.x; j < Nn; j += blockDim.x) {
        float acc = bm[j];
        for (int k = 0; k < K; k++) acc += arow[k] * Wm[k * Nn + j];
        if (do_relu) acc = fmaxf(acc, 0.f);
        out[g * Nn + j] = acc;
    }
}

// ---------------- launch ------------------------------------------------------
extern "C" void kernel_launch(void* const* d_in, const int* in_sizes, int n_in,
                              void* d_out, int out_size) {
    const float* x    = (const float*)d_in[0];
    const int*   ei   = (const int*)d_in[1];
    const int*   batch= (const int*)d_in[2];
    const float *W[5], *as_[5], *ad_[5], *bc_[5];
    for (int i = 0; i < 5; i++) {
        W[i]   = (const float*)d_in[3 + 4 * i];
        as_[i] = (const float*)d_in[4 + 4 * i];
        ad_[i] = (const float*)d_in[5 + 4 * i];
        bc_[i] = (const float*)d_in[6 + 4 * i];
    }
    const float* lw1 = (const float*)d_in[23];
    const float* lb1 = (const float*)d_in[24];
    const float* lw2 = (const float*)d_in[25];
    const float* lb2 = (const float*)d_in[26];
    const float* lw3 = (const float*)d_in[27];
    const float* lb3 = (const float*)d_in[28];

    float *px, *ph, *ppool, *pt1, *pt2;
    cudaGetSymbolAddress((void**)&px, g_x);
    cudaGetSymbolAddress((void**)&ph, g_h);
    cudaGetSymbolAddress((void**)&ppool, g_pool);
    cudaGetSymbolAddress((void**)&pt1, g_t1);
    cudaGetSymbolAddress((void**)&pt2, g_t2);

    // CSR (fixed topology, rebuilt each launch for determinism)
    k_init_cnt<<<(N_NODES + 255) / 256, 256>>>();
    k_count<<<(E_EDGES + 255) / 256, 256>>>(ei);
    k_scan<<<1, 1024>>>();
    k_scatter<<<(E_TOT + 255) / 256, 256>>>(ei);

    const float* xin = x;
    int K = F_IN;
    int warpGrid = (N_NODES * 32 + 255) / 256;
    for (int l = 0; l < 5; l++) {
        dim3 grid((HC + 63) / 64, (N_NODES + 63) / 64);
        k_sgemm<<<grid, 256>>>(xin, W[l], ph, N_NODES, K, HC);
        k_scores<<<warpGrid, 256>>>(as_[l], ad_[l]);
        k_aggregate<<<warpGrid, 256>>>(bc_[l]);
        xin = px;
        K = HC;
    }

    k_pool_zero<<<(G_GRAPHS * HC + 255) / 256, 256>>>();
    k_pool<<<(N_NODES * HC + 255) / 256, 256>>>(batch);

    k_mlp<<<G_GRAPHS, 128>>>(ppool, lw1, lb1, pt1, 200, 100, 1, 1);
    k_mlp<<<G_GRAPHS, 128>>>(pt1, lw2, lb2, pt2, 100, 100, 1, 0);
    k_mlp<<<G_GRAPHS, 128>>>(pt2, lw3, lb3, (float*)d_out, 100, 29, 0, 0);
}

// round 2
// speedup vs baseline: 1.7277x; 1.7277x over previous
#include <cuda_runtime.h>
#include <cuda_bf16.h>
#include <cstdint>

#define N_NODES 50000
#define E_EDGES 400000
#define E_TOT   450000   // edges + self loops
#define G_GRAPHS 256
#define HC 200           // H*C
#define C_CH 100
#define F_IN 336
#define SLOPE 0.2f

// ---------------- scratch (device globals: no allocation allowed) -------------
__device__ float g_x[N_NODES * HC];       // layer output (post-relu)
__device__ float g_h[N_NODES * HC];       // per-layer linear output
__device__ float g_es[N_NODES * 2];
__device__ float g_ed[N_NODES * 2];
__device__ float g_alpha[E_TOT * 2];
__device__ int   g_cnt[N_NODES];
__device__ int   g_rowptr[N_NODES + 1];
__device__ int   g_wr[N_NODES];
__device__ int   g_srcidx[E_TOT];
__device__ float g_pool[G_GRAPHS * HC];
__device__ int   g_pcnt[G_GRAPHS];
__device__ float g_t1[G_GRAPHS * 100];
__device__ float g_t2[G_GRAPHS * 100];

// ---------------- CSR build ---------------------------------------------------
__global__ void k_init_cnt() {
    int i = blockIdx.x * blockDim.x + threadIdx.x;
    if (i < N_NODES) g_cnt[i] = 1;   // self-loop
}

__global__ void k_count(const int* __restrict__ ei) {
    int e = blockIdx.x * blockDim.x + threadIdx.x;
    if (e < E_EDGES) atomicAdd(&g_cnt[ei[E_EDGES + e]], 1);
}

__global__ void k_scan() {   // single block, 1024 threads
    const int n = N_NODES;
    int t = threadIdx.x;
    const int CHUNK = (n + 1023) / 1024;
    int start = t * CHUNK;
    int end = min(start + CHUNK, n);
    int sum = 0;
    for (int i = start; i < end; i++) sum += g_cnt[i];
    __shared__ int sh[1024];
    sh[t] = sum;
    __syncthreads();
    for (int off = 1; off < 1024; off <<= 1) {
        int v = (t >= off) ? sh[t - off] : 0;
        __syncthreads();
        sh[t] += v;
        __syncthreads();
    }
    int run = sh[t] - sum;   // exclusive
    for (int i = start; i < end; i++) {
        g_rowptr[i] = run;
        g_wr[i] = run;
        run += g_cnt[i];
    }
    if (t == 1023) g_rowptr[n] = sh[1023];
}

__global__ void k_scatter(const int* __restrict__ ei) {
    int e = blockIdx.x * blockDim.x + threadIdx.x;
    if (e >= E_TOT) return;
    int s, d;
    if (e < E_EDGES) { s = ei[e]; d = ei[E_EDGES + e]; }
    else             { s = d = e - E_EDGES; }
    int pos = atomicAdd(&g_wr[d], 1);
    g_srcidx[pos] = s;
}

// ---------------- tf32x3 tensor-core GEMM ------------------------------------
// C[M,Nn] = A[M,K] @ B[K,Nn], fp32-accurate via hi/lo tf32 split (3 mma).
__device__ __forceinline__ void split_tf32(float v, uint32_t& hi, uint32_t& lo) {
    asm("cvt.rna.tf32.f32 %0, %1;" : "=r"(hi) : "f"(v));
    float h = __uint_as_float(hi);
    float r = v - h;
    asm("cvt.rna.tf32.f32 %0, %1;" : "=r"(lo) : "f"(r));
}

__device__ __forceinline__ void mma_tf32(float* c,
                                         const uint32_t* a, const uint32_t* b) {
    asm volatile(
        "mma.sync.aligned.m16n8k8.row.col.f32.tf32.tf32.f32 "
        "{%0,%1,%2,%3},{%4,%5,%6,%7},{%8,%9},{%0,%1,%2,%3};"
        : "+f"(c[0]), "+f"(c[1]), "+f"(c[2]), "+f"(c[3])
        : "r"(a[0]), "r"(a[1]), "r"(a[2]), "r"(a[3]), "r"(b[0]), "r"(b[1]));
}

__global__ void __launch_bounds__(256)
k_gemm_tf32(const float* __restrict__ A, const float* __restrict__ B,
            float* __restrict__ C, int M, int K, int Nn)
{
    const int BM = 128, BN = 64, BK = 32;
    __shared__ float As[BM][36];   // [m][k], stride 36 -> conflict-free frag loads
    __shared__ float Bs[BK][72];   // [k][n], stride 72 -> conflict-free frag loads

    int tid = threadIdx.x;
    int rowBase = blockIdx.y * BM;
    int colBase = blockIdx.x * BN;
    int warpId = tid >> 5, lane = tid & 31;
    int wm = (warpId & 3) * 32;        // warp row offset in tile
    int wn = (warpId >> 2) * 32;       // warp col offset in tile
    int gr = lane >> 2;                // groupID 0..7
    int cq = lane & 3;                 // threadID_in_group 0..3

    float acc[2][4][4];
#pragma unroll
    for (int i = 0; i < 2; i++)
#pragma unroll
        for (int j = 0; j < 4; j++)
#pragma unroll
            for (int k = 0; k < 4; k++) acc[i][j][k] = 0.f;

    int arow = tid >> 3;               // 0..31
    int acol = (tid & 7) * 4;          // 0..28
    int brow = tid >> 4;               // 0..15
    int bcol = (tid & 15) * 4;         // 0..60

    for (int k0 = 0; k0 < K; k0 += BK) {
        // stage A tile (128x32)
#pragma unroll
        for (int i = 0; i < 4; i++) {
            int m = arow + i * 32;
            int gm = rowBase + m;
            float4 v = make_float4(0.f, 0.f, 0.f, 0.f);
            if (gm < M && (k0 + acol) < K)
                v = *(const float4*)(A + (long)gm * K + k0 + acol);
            *(float4*)&As[m][acol] = v;
        }
        // stage B tile (32x64)
#pragma unroll
        for (int i = 0; i < 2; i++) {
            int kk = brow + i * 16;
            int gk = k0 + kk;
            float4 v = make_float4(0.f, 0.f, 0.f, 0.f);
            if (gk < K && (colBase + bcol) < Nn)
                v = *(const float4*)(B + (long)gk * Nn + colBase + bcol);
            *(float4*)&Bs[kk][bcol] = v;
        }
        __syncthreads();

#pragma unroll
        for (int ks = 0; ks < 4; ks++) {
            int kb = ks * 8 + cq;
            uint32_t ah[2][4], al[2][4];
#pragma unroll
            for (int mt = 0; mt < 2; mt++) {
                int m = wm + mt * 16 + gr;
                split_tf32(As[m][kb],         ah[mt][0], al[mt][0]);
                split_tf32(As[m + 8][kb],     ah[mt][1], al[mt][1]);
                split_tf32(As[m][kb + 4],     ah[mt][2], al[mt][2]);
                split_tf32(As[m + 8][kb + 4], ah[mt][3], al[mt][3]);
            }
            uint32_t bh[4][2], bl[4][2];
#pragma unroll
            for (int nt = 0; nt < 4; nt++) {
                int n = wn + nt * 8 + gr;
                split_tf32(Bs[kb][n],     bh[nt][0], bl[nt][0]);
                split_tf32(Bs[kb + 4][n], bh[nt][1], bl[nt][1]);
            }
#pragma unroll
            for (int mt = 0; mt < 2; mt++)
#pragma unroll
                for (int nt = 0; nt < 4; nt++) {
                    float* c = acc[mt][nt];
                    mma_tf32(c, al[mt], bh[nt]);   // lo*hi
                    mma_tf32(c, ah[mt], bl[nt]);   // hi*lo
                    mma_tf32(c, ah[mt], bh[nt]);   // hi*hi
                }
        }
        __syncthreads();
    }

    // store C
#pragma unroll
    for (int mt = 0; mt < 2; mt++) {
#pragma unroll
        for (int nt = 0; nt < 4; nt++) {
            int row = rowBase + wm + mt * 16 + gr;
            int col = colBase + wn + nt * 8 + cq * 2;
            float* c = acc[mt][nt];
            if (col < Nn) {
                if (row < M) {
                    float2 v = make_float2(c[0], c[1]);
                    *(float2*)(C + (long)row * Nn + col) = v;
                }
                if (row + 8 < M) {
                    float2 v = make_float2(c[2], c[3]);
                    *(float2*)(C + (long)(row + 8) * Nn + col) = v;
                }
            }
        }
    }
}

// ---------------- attention source/dest scores (warp per node) ----------------
__global__ void k_scores(const float* __restrict__ asrc, const float* __restrict__ adst) {
    int gwarp = (blockIdx.x * blockDim.x + threadIdx.x) >> 5;
    int lane  = threadIdx.x & 31;
    if (gwarp >= N_NODES) return;
    const float* hr = g_h + (long)gwarp * HC;
    float es0 = 0.f, es1 = 0.f, ed0 = 0.f, ed1 = 0.f;
    for (int c = lane; c < HC; c += 32) {
        float v = hr[c], a = asrc[c], d = adst[c];
        if (c < C_CH) { es0 += v * a; ed0 += v * d; }
        else          { es1 += v * a; ed1 += v * d; }
    }
#pragma unroll
    for (int o = 16; o; o >>= 1) {
        es0 += __shfl_xor_sync(0xffffffffu, es0, o);
        es1 += __shfl_xor_sync(0xffffffffu, es1, o);
        ed0 += __shfl_xor_sync(0xffffffffu, ed0, o);
        ed1 += __shfl_xor_sync(0xffffffffu, ed1, o);
    }
    if (lane == 0) {
        g_es[gwarp * 2]     = es0;
        g_es[gwarp * 2 + 1] = es1;
        g_ed[gwarp * 2]     = ed0;
        g_ed[gwarp * 2 + 1] = ed1;
    }
}

// ---------------- softmax + aggregate + bias + relu (warp per dst) ------------
__device__ __forceinline__ float lrelu(float e) { return e > 0.f ? e : SLOPE * e; }

__global__ void k_aggregate(const float* __restrict__ bc) {
    int gwarp = (blockIdx.x * blockDim.x + threadIdx.x) >> 5;
    int lane  = threadIdx.x & 31;
    if (gwarp >= N_NODES) return;
    int dst = gwarp;
    int beg = g_rowptr[dst], end = g_rowptr[dst + 1];
    float ed0 = g_ed[dst * 2], ed1 = g_ed[dst * 2 + 1];

    float m0 = -1e30f, m1 = -1e30f;
    for (int i = beg + lane; i < end; i += 32) {
        int s = g_srcidx[i];
        m0 = fmaxf(m0, lrelu(g_es[s * 2]     + ed0));
        m1 = fmaxf(m1, lrelu(g_es[s * 2 + 1] + ed1));
    }
#pragma unroll
    for (int o = 16; o; o >>= 1) {
        m0 = fmaxf(m0, __shfl_xor_sync(0xffffffffu, m0, o));
        m1 = fmaxf(m1, __shfl_xor_sync(0xffffffffu, m1, o));
    }

    float s0 = 0.f, s1 = 0.f;
    for (int i = beg + lane; i < end; i += 32) {
        int s = g_srcidx[i];
        float p0 = __expf(lrelu(g_es[s * 2]     + ed0) - m0);
        float p1 = __expf(lrelu(g_es[s * 2 + 1] + ed1) - m1);
        g_alpha[i * 2]     = p0;
        g_alpha[i * 2 + 1] = p1;
        s0 += p0; s1 += p1;
    }
#pragma unroll
    for (int o = 16; o; o >>= 1) {
        s0 += __shfl_xor_sync(0xffffffffu, s0, o);
        s1 += __shfl_xor_sync(0xffffffffu, s1, o);
    }
    float inv0 = 1.f / (s0 + 1e-16f);
    float inv1 = 1.f / (s1 + 1e-16f);

    float acc[7] = {0.f, 0.f, 0.f, 0.f, 0.f, 0.f, 0.f};
    for (int i = beg; i < end; i++) {
        int s = g_srcidx[i];
        float a0 = g_alpha[i * 2]     * inv0;
        float a1 = g_alpha[i * 2 + 1] * inv1;
        const float* hr = g_h + (long)s * HC;
#pragma unroll
        for (int k = 0; k < 7; k++) {
            int c = lane + k * 32;
            if (c < HC) acc[k] += (c < C_CH ? a0 : a1) * hr[c];
        }
    }
#pragma unroll
    for (int k = 0; k < 7; k++) {
        int c = lane + k * 32;
        if (c < HC) g_x[(long)dst * HC + c] = fmaxf(acc[k] + bc[c], 0.f);
    }
}

// ---------------- mean pool ---------------------------------------------------
__global__ void k_pool_zero() {
    int i = blockIdx.x * blockDim.x + threadIdx.x;
    if (i < G_GRAPHS * HC) g_pool[i] = 0.f;
    if (i < G_GRAPHS) g_pcnt[i] = 0;
}

__global__ void k_pool(const int* __restrict__ batch) {
    int i = blockIdx.x * blockDim.x + threadIdx.x;
    if (i >= N_NODES * HC) return;
    int n = i / HC, c = i - n * HC;
    int b = batch[n];
    atomicAdd(&g_pool[b * HC + c], g_x[i]);
    if (c == 0) atomicAdd(&g_pcnt[b], 1);
}

// ---------------- tiny MLP layer (one block per graph) ------------------------
__global__ void k_mlp(const float* __restrict__ A, const float* __restrict__ Wm,
                      const float* __restrict__ bm, float* __restrict__ out,
                      int K, int Nn, int do_relu, int do_div) {
    int g = blockIdx.x;
    __shared__ float arow[HC];
    float inv = 1.f;
    if (do_div) inv = 1.f / fmaxf((float)g_pcnt[g], 1.f);
    for (int i = threadIdx.x; i < K; i += blockDim.x) arow[i] = A[g * K + i] * inv;
    __syncthreads();
    for (int j = threadIdx.x; j < Nn; j += blockDim.x) {
        float acc = bm[j];
        for (int k = 0; k < K; k++) acc += arow[k] * Wm[k * Nn + j];
        if (do_relu) acc = fmaxf(acc, 0.f);
        out[g * Nn + j] = acc;
    }
}

// ---------------- launch ------------------------------------------------------
extern "C" void kernel_launch(void* const* d_in, const int* in_sizes, int n_in,
                              void* d_out, int out_size) {
    const float* x    = (const float*)d_in[0];
    const int*   ei   = (const int*)d_in[1];
    const int*   batch= (const int*)d_in[2];
    const float *W[5], *as_[5], *ad_[5], *bc_[5];
    for (int i = 0; i < 5; i++) {
        W[i]   = (const float*)d_in[3 + 4 * i];
        as_[i] = (const float*)d_in[4 + 4 * i];
        ad_[i] = (const float*)d_in[5 + 4 * i];
        bc_[i] = (const float*)d_in[6 + 4 * i];
    }
    const float* lw1 = (const float*)d_in[23];
    const float* lb1 = (const float*)d_in[24];
    const float* lw2 = (const float*)d_in[25];
    const float* lb2 = (const float*)d_in[26];
    const float* lw3 = (const float*)d_in[27];
    const float* lb3 = (const float*)d_in[28];

    float *px, *ph, *ppool, *pt1, *pt2;
    cudaGetSymbolAddress((void**)&px, g_x);
    cudaGetSymbolAddress((void**)&ph, g_h);
    cudaGetSymbolAddress((void**)&ppool, g_pool);
    cudaGetSymbolAddress((void**)&pt1, g_t1);
    cudaGetSymbolAddress((void**)&pt2, g_t2);

    // CSR (fixed topology, rebuilt each launch for determinism)
    k_init_cnt<<<(N_NODES + 255) / 256, 256>>>();
    k_count<<<(E_EDGES + 255) / 256, 256>>>(ei);
    k_scan<<<1, 1024>>>();
    k_scatter<<<(E_TOT + 255) / 256, 256>>>(ei);

    const float* xin = x;
    int K = F_IN;
    int warpGrid = (N_NODES * 32 + 255) / 256;
    for (int l = 0; l < 5; l++) {
        dim3 grid((HC + 63) / 64, (N_NODES + 127) / 128);
        k_gemm_tf32<<<grid, 256>>>(xin, W[l], ph, N_NODES, K, HC);
        k_scores<<<warpGrid, 256>>>(as_[l], ad_[l]);
        k_aggregate<<<warpGrid, 256>>>(bc_[l]);
        xin = px;
        K = HC;
    }

    k_pool_zero<<<(G_GRAPHS * HC + 255) / 256, 256>>>();
    k_pool<<<(N_NODES * HC + 255) / 256, 256>>>(batch);

    k_mlp<<<G_GRAPHS, 128>>>(ppool, lw1, lb1, pt1, 200, 100, 1, 1);
    k_mlp<<<G_GRAPHS, 128>>>(pt1, lw2, lb2, pt2, 100, 100, 1, 0);
    k_mlp<<<G_GRAPHS, 128>>>(pt2, lw3, lb3, (float*)d_out, 100, 29, 0, 0);
}